// round 3
// baseline (speedup 1.0000x reference)
#include <cuda_runtime.h>
#include <cstdint>

#define BATCH 64
#define LDIM  256
#define HDIM  1024
#define DDIM  1024
#define MNZ   33
#define NOUT  (DDIM*MNZ)   // 33792

// scratch (device globals: no allocation allowed)
__device__ float g_h[BATCH*HDIM];   // 256 KB
__device__ float g_v[BATCH*NOUT];   // 8.6 MB

// ---------------------------------------------------------------------------
// Kernel 1: h = gelu(z @ W1 + b1), exact (erf) GELU.
// Latency-bound problem (1.3 MB total traffic) -> maximize parallelism + MLP.
// 128 blocks x 256 threads; thread = (jl in 0..7, bq in 0..31), 2 outputs
// (b = bq and bq+32). No smem: z rows are L1-resident float4 streams, W1
// reads are 32B/warp sectors read once globally.
// ---------------------------------------------------------------------------
__global__ void __launch_bounds__(256) k1_mlp_gelu(
        const float* __restrict__ z,
        const float* __restrict__ W1,
        const float* __restrict__ b1) {
    const int t  = threadIdx.x;
    const int jl = t & 7;
    const int bq = t >> 3;                 // 0..31
    const int j  = blockIdx.x * 8 + jl;

    const float* zr0 = z + bq * LDIM;
    const float* zr1 = z + (bq + 32) * LDIM;
    const float* wp  = W1 + j;

    float a0 = 0.f, a1 = 0.f;
    #pragma unroll
    for (int k = 0; k < LDIM; k += 8) {
        float4 za = *reinterpret_cast<const float4*>(zr0 + k);
        float4 zb = *reinterpret_cast<const float4*>(zr0 + k + 4);
        float4 zc = *reinterpret_cast<const float4*>(zr1 + k);
        float4 zd = *reinterpret_cast<const float4*>(zr1 + k + 4);
        float w0 = __ldg(wp + (k + 0) * HDIM);
        float w1 = __ldg(wp + (k + 1) * HDIM);
        float w2 = __ldg(wp + (k + 2) * HDIM);
        float w3 = __ldg(wp + (k + 3) * HDIM);
        float w4 = __ldg(wp + (k + 4) * HDIM);
        float w5 = __ldg(wp + (k + 5) * HDIM);
        float w6 = __ldg(wp + (k + 6) * HDIM);
        float w7 = __ldg(wp + (k + 7) * HDIM);
        a0 += za.x * w0 + za.y * w1 + za.z * w2 + za.w * w3
            + zb.x * w4 + zb.y * w5 + zb.z * w6 + zb.w * w7;
        a1 += zc.x * w0 + zc.y * w1 + zc.z * w2 + zc.w * w3
            + zd.x * w4 + zd.y * w5 + zd.z * w6 + zd.w * w7;
    }
    const float bias = __ldg(b1 + j);
    float x0 = a0 + bias, x1 = a1 + bias;
    g_h[bq        * HDIM + j] = 0.5f * x0 * (1.0f + erff(x0 * 0.70710678118654752f));
    g_h[(bq + 32) * HDIM + j] = 0.5f * x1 * (1.0f + erff(x1 * 0.70710678118654752f));
}

// ---------------------------------------------------------------------------
// Kernel 2: v = h @ W2 + b2  (64 x 33792, K=1024), tf32 mma.sync, fp32 accum.
// CTA tile 64x256, 256 threads (8 warps x 64x32), BK=16, 3-stage cp.async.
// grid = 132 CTAs = single wave on 148 SMs (no tail).
// ---------------------------------------------------------------------------
#define BN 256
#define BK 16
#define STAGES 3
#define ASTRIDE 20            // 64 rows x (16+4)
#define BSTRIDE (BN + 4)      // 260
#define A_ELEMS (64 * ASTRIDE)
#define B_ELEMS (BK * BSTRIDE)
#define NSTAGE (HDIM / BK)    // 64
#define K2_SMEM (STAGES * (A_ELEMS + B_ELEMS) * 4)   // 65280 B

__device__ __forceinline__ void cp16(float* s, const float* g) {
    uint32_t a = (uint32_t)__cvta_generic_to_shared(s);
    asm volatile("cp.async.cg.shared.global [%0], [%1], 16;\n" :: "r"(a), "l"(g));
}
__device__ __forceinline__ uint32_t f2tf(float x) {
    uint32_t r; asm("cvt.rna.tf32.f32 %0, %1;\n" : "=r"(r) : "f"(x)); return r;
}
__device__ __forceinline__ void mma8(float* d, const uint32_t* a, uint32_t b0, uint32_t b1) {
    asm volatile("mma.sync.aligned.m16n8k8.row.col.f32.tf32.tf32.f32 "
                 "{%0,%1,%2,%3}, {%4,%5,%6,%7}, {%8,%9}, {%0,%1,%2,%3};\n"
                 : "+f"(d[0]), "+f"(d[1]), "+f"(d[2]), "+f"(d[3])
                 : "r"(a[0]), "r"(a[1]), "r"(a[2]), "r"(a[3]), "r"(b0), "r"(b1));
}

__global__ void __launch_bounds__(256) k2_gemm(const float* __restrict__ W2,
                                               const float* __restrict__ b2) {
    extern __shared__ float sm2[];
    float* Asm = sm2;                          // [STAGES][A_ELEMS]
    float* Bsm = sm2 + STAGES * A_ELEMS;       // [STAGES][B_ELEMS]
    const int t    = threadIdx.x;
    const int wid  = t >> 5;
    const int lane = t & 31;
    const int n0   = blockIdx.x * BN;
    const int r = lane >> 2, c = lane & 3;

    float acc[4][4][4];
    #pragma unroll
    for (int i = 0; i < 4; i++)
        #pragma unroll
        for (int j = 0; j < 4; j++)
            #pragma unroll
            for (int e = 0; e < 4; e++) acc[i][j][e] = 0.f;

    auto load_stage = [&](int s, int buf) {
        const int k0 = s * BK;
        {   // A: 64x16 = 256 float4 -> 1 per thread
            int m = t >> 2, kk4 = (t & 3) * 4;
            cp16(&Asm[buf * A_ELEMS + m * ASTRIDE + kk4], g_h + m * HDIM + k0 + kk4);
        }
        #pragma unroll
        for (int i = 0; i < 4; i++) {           // B: 16x256 = 1024 float4
            int f = t + 256 * i;
            int kk = f >> 6, nn4 = (f & 63) * 4;
            cp16(&Bsm[buf * B_ELEMS + kk * BSTRIDE + nn4], W2 + (k0 + kk) * NOUT + n0 + nn4);
        }
        asm volatile("cp.async.commit_group;\n" ::: "memory");
    };

    load_stage(0, 0);
    load_stage(1, 1);
    int buf = 0;
    #pragma unroll 1
    for (int s = 0; s < NSTAGE; s++) {
        if (s + 2 < NSTAGE) {
            load_stage(s + 2, (buf + 2) % STAGES);
            asm volatile("cp.async.wait_group 2;\n" ::: "memory");
        } else if (s + 1 < NSTAGE) {
            asm volatile("cp.async.wait_group 1;\n" ::: "memory");
        } else {
            asm volatile("cp.async.wait_group 0;\n" ::: "memory");
        }
        __syncthreads();
        const float* A  = Asm + buf * A_ELEMS;
        const float* Bb = Bsm + buf * B_ELEMS;
        #pragma unroll
        for (int kk = 0; kk < BK; kk += 8) {
            uint32_t af[4][4];
            #pragma unroll
            for (int mt = 0; mt < 4; mt++) {
                int mr = mt * 16 + r;
                af[mt][0] = f2tf(A[mr       * ASTRIDE + kk + c]);
                af[mt][1] = f2tf(A[(mr + 8) * ASTRIDE + kk + c]);
                af[mt][2] = f2tf(A[mr       * ASTRIDE + kk + c + 4]);
                af[mt][3] = f2tf(A[(mr + 8) * ASTRIDE + kk + c + 4]);
            }
            #pragma unroll
            for (int nt = 0; nt < 4; nt++) {
                int nb = wid * 32 + nt * 8 + r;
                uint32_t b0 = f2tf(Bb[(kk + c)     * BSTRIDE + nb]);
                uint32_t b1 = f2tf(Bb[(kk + c + 4) * BSTRIDE + nb]);
                #pragma unroll
                for (int mt = 0; mt < 4; mt++)
                    mma8(acc[mt][nt], af[mt], b0, b1);
            }
        }
        __syncthreads();
        buf = (buf + 1) % STAGES;
    }

    // epilogue: add bias, store float2 pairs
    #pragma unroll
    for (int nt = 0; nt < 4; nt++) {
        int n = n0 + wid * 32 + nt * 8 + c * 2;
        float bx = b2[n], by = b2[n + 1];
        #pragma unroll
        for (int mt = 0; mt < 4; mt++) {
            int m = mt * 16 + r;
            float2 o0 = make_float2(acc[mt][nt][0] + bx, acc[mt][nt][1] + by);
            float2 o1 = make_float2(acc[mt][nt][2] + bx, acc[mt][nt][3] + by);
            *reinterpret_cast<float2*>(&g_v[m       * NOUT + n]) = o0;
            *reinterpret_cast<float2*>(&g_v[(m + 8) * NOUT + n]) = o1;
        }
    }
}

// ---------------------------------------------------------------------------
// Kernel 3: dense output writer. One block per (b,i) row; float4 streaming
// stores (__stcs: 268 MB write-once should not churn L2; g_v stays resident).
// k[b,i,j] = 0.5*(v[b,i,j-lo_i] + v[b,j,i-lo_j]) + (i==j), |i-j|<=16, else 0.
// ---------------------------------------------------------------------------
__global__ void __launch_bounds__(256) k3_scatter(float* __restrict__ out) {
    const int bi = blockIdx.x;            // b*1024 + i
    const int i  = bi & (DDIM - 1);
    const int b  = bi >> 10;
    const int t  = threadIdx.x;
    const int j0 = t * 4;
    const int lo = (i > 16) ? i - 16 : 0;
    const int hi = (i < DDIM - 17) ? i + 16 : DDIM - 1;

    float4 val = make_float4(0.f, 0.f, 0.f, 0.f);
    if (j0 + 3 >= lo && j0 <= hi) {
        const float* vb = g_v + b * NOUT;
        float rr[4];
        #pragma unroll
        for (int e = 0; e < 4; e++) {
            int j = j0 + e;
            float x = 0.f;
            if (j >= lo && j <= hi) {
                float t1  = vb[i * MNZ + (j - lo)];
                int   loj = (j > 16) ? j - 16 : 0;
                float t2  = vb[j * MNZ + (i - loj)];
                x = 0.5f * (t1 + t2);
                if (j == i) x += 1.0f;
            }
            rr[e] = x;
        }
        val = make_float4(rr[0], rr[1], rr[2], rr[3]);
    }
    __stcs(reinterpret_cast<float4*>(out + (size_t)bi * DDIM) + t, val);
}

// ---------------------------------------------------------------------------
extern "C" void kernel_launch(void* const* d_in, const int* in_sizes, int n_in,
                              void* d_out, int out_size) {
    const float* z  = (const float*)d_in[0];
    // d_in[1] = mask (unused: band structure is analytic)
    const float* W1 = (const float*)d_in[2];
    const float* b1 = (const float*)d_in[3];
    const float* W2 = (const float*)d_in[4];
    const float* b2 = (const float*)d_in[5];
    // d_in[6] = idx (unused: idx[i][m] == max(0,i-16)+m on the valid range)
    float* out = (float*)d_out;

    cudaFuncSetAttribute(k2_gemm,
                         cudaFuncAttributeMaxDynamicSharedMemorySize, K2_SMEM);
    k1_mlp_gelu<<<HDIM / 8, 256>>>(z, W1, b1);
    k2_gemm<<<NOUT / BN, 256, K2_SMEM>>>(W2, b2);
    k3_scatter<<<BATCH * DDIM, 256>>>(out);
}

// round 4
// speedup vs baseline: 1.2216x; 1.2216x over previous
#include <cuda_runtime.h>
#include <cstdint>

#define BATCH 64
#define LDIM  256
#define HDIM  1024
#define DDIM  1024
#define MNZ   33
#define NOUT  (DDIM*MNZ)   // 33792

// scratch (device globals: no allocation allowed)
__device__ float g_h[BATCH*HDIM];   // 256 KB (stored pre-rounded to tf32)
__device__ float g_v[BATCH*NOUT];   // 8.6 MB

__device__ __forceinline__ uint32_t f2tf(float x) {
    uint32_t r; asm("cvt.rna.tf32.f32 %0, %1;\n" : "=r"(r) : "f"(x)); return r;
}

// ---------------------------------------------------------------------------
// Kernel 1: h = gelu(z @ W1 + b1), exact (erf) GELU. Coalescing-first:
// warp lanes = consecutive j -> every W1[k][j..j+31] load is a 128B line.
// 128 blocks x 256 thr: block = (jb in 0..3 -> 256 j) x (bg in 0..31 -> 2 b).
// z rows staged in smem, broadcast on read. Output pre-rounded to tf32 so
// k2 can skip A-side cvt.
// ---------------------------------------------------------------------------
__global__ void __launch_bounds__(256) k1_mlp_gelu(
        const float* __restrict__ z,
        const float* __restrict__ W1,
        const float* __restrict__ b1) {
    __shared__ float sz[2 * LDIM];
    const int tid = threadIdx.x;
    const int jb  = blockIdx.x & 3;
    const int bg  = blockIdx.x >> 2;          // 0..31
    const int j   = jb * 256 + tid;
    const int b0  = bg * 2;

    #pragma unroll
    for (int i = tid; i < 2 * LDIM; i += 256)
        sz[i] = z[(b0 + (i >> 8)) * LDIM + (i & (LDIM - 1))];
    __syncthreads();

    const float* wp = W1 + j;
    float a0 = 0.f, a1 = 0.f;
    #pragma unroll 8
    for (int k = 0; k < LDIM; k++) {
        float w = wp[k * HDIM];               // coalesced 128B per warp
        a0 += sz[k] * w;                      // smem broadcast
        a1 += sz[LDIM + k] * w;
    }
    const float bias = b1[j];
    float x0 = a0 + bias, x1 = a1 + bias;
    float h0 = 0.5f * x0 * (1.0f + erff(x0 * 0.70710678118654752f));
    float h1 = 0.5f * x1 * (1.0f + erff(x1 * 0.70710678118654752f));
    g_h[b0       * HDIM + j] = __uint_as_float(f2tf(h0));
    g_h[(b0 + 1) * HDIM + j] = __uint_as_float(f2tf(h1));
}

// ---------------------------------------------------------------------------
// Kernel 2: v = h @ W2 + b2  (64 x 33792, K=1024), tf32 mma.sync, fp32 accum.
// CTA tile 64x256, 256 threads (8 warps x 64x32), BK=16, 3-stage cp.async.
// grid = 132 CTAs = single wave. A fragments are pre-rounded tf32 bits
// (no cvt in inner loop); B converted with cvt.rna.
// ---------------------------------------------------------------------------
#define BN 256
#define BK 16
#define STAGES 3
#define ASTRIDE 20            // 64 rows x (16+4)
#define BSTRIDE (BN + 4)      // 260
#define A_ELEMS (64 * ASTRIDE)
#define B_ELEMS (BK * BSTRIDE)
#define NSTAGE (HDIM / BK)    // 64
#define K2_SMEM (STAGES * (A_ELEMS + B_ELEMS) * 4)   // 65280 B

__device__ __forceinline__ void cp16(float* s, const float* g) {
    uint32_t a = (uint32_t)__cvta_generic_to_shared(s);
    asm volatile("cp.async.cg.shared.global [%0], [%1], 16;\n" :: "r"(a), "l"(g));
}
__device__ __forceinline__ void mma8(float* d, const uint32_t* a, uint32_t b0, uint32_t b1) {
    asm volatile("mma.sync.aligned.m16n8k8.row.col.f32.tf32.tf32.f32 "
                 "{%0,%1,%2,%3}, {%4,%5,%6,%7}, {%8,%9}, {%0,%1,%2,%3};\n"
                 : "+f"(d[0]), "+f"(d[1]), "+f"(d[2]), "+f"(d[3])
                 : "r"(a[0]), "r"(a[1]), "r"(a[2]), "r"(a[3]), "r"(b0), "r"(b1));
}

__global__ void __launch_bounds__(256) k2_gemm(const float* __restrict__ W2,
                                               const float* __restrict__ b2) {
    extern __shared__ float sm2[];
    float* Asm = sm2;                          // [STAGES][A_ELEMS]
    float* Bsm = sm2 + STAGES * A_ELEMS;       // [STAGES][B_ELEMS]
    const int t    = threadIdx.x;
    const int wid  = t >> 5;
    const int lane = t & 31;
    const int n0   = blockIdx.x * BN;
    const int r = lane >> 2, c = lane & 3;

    float acc[4][4][4];
    #pragma unroll
    for (int i = 0; i < 4; i++)
        #pragma unroll
        for (int j = 0; j < 4; j++)
            #pragma unroll
            for (int e = 0; e < 4; e++) acc[i][j][e] = 0.f;

    auto load_stage = [&](int s, int buf) {
        const int k0 = s * BK;
        {   // A: 64x16 = 256 float4 -> 1 per thread
            int m = t >> 2, kk4 = (t & 3) * 4;
            cp16(&Asm[buf * A_ELEMS + m * ASTRIDE + kk4], g_h + m * HDIM + k0 + kk4);
        }
        #pragma unroll
        for (int i = 0; i < 4; i++) {           // B: 16x256 = 1024 float4
            int f = t + 256 * i;
            int kk = f >> 6, nn4 = (f & 63) * 4;
            cp16(&Bsm[buf * B_ELEMS + kk * BSTRIDE + nn4], W2 + (k0 + kk) * NOUT + n0 + nn4);
        }
        asm volatile("cp.async.commit_group;\n" ::: "memory");
    };

    load_stage(0, 0);
    load_stage(1, 1);
    int buf = 0;
    #pragma unroll 1
    for (int s = 0; s < NSTAGE; s++) {
        if (s + 2 < NSTAGE) {
            load_stage(s + 2, (buf + 2) % STAGES);
            asm volatile("cp.async.wait_group 2;\n" ::: "memory");
        } else if (s + 1 < NSTAGE) {
            asm volatile("cp.async.wait_group 1;\n" ::: "memory");
        } else {
            asm volatile("cp.async.wait_group 0;\n" ::: "memory");
        }
        __syncthreads();
        const uint32_t* A = reinterpret_cast<const uint32_t*>(Asm + buf * A_ELEMS);
        const float*    Bb = Bsm + buf * B_ELEMS;
        #pragma unroll
        for (int kk = 0; kk < BK; kk += 8) {
            uint32_t af[4][4];
            #pragma unroll
            for (int mt = 0; mt < 4; mt++) {
                int mr = mt * 16 + r;
                af[mt][0] = A[mr       * ASTRIDE + kk + c];
                af[mt][1] = A[(mr + 8) * ASTRIDE + kk + c];
                af[mt][2] = A[mr       * ASTRIDE + kk + c + 4];
                af[mt][3] = A[(mr + 8) * ASTRIDE + kk + c + 4];
            }
            #pragma unroll
            for (int nt = 0; nt < 4; nt++) {
                int nb = wid * 32 + nt * 8 + r;
                uint32_t b0 = f2tf(Bb[(kk + c)     * BSTRIDE + nb]);
                uint32_t b1 = f2tf(Bb[(kk + c + 4) * BSTRIDE + nb]);
                #pragma unroll
                for (int mt = 0; mt < 4; mt++)
                    mma8(acc[mt][nt], af[mt], b0, b1);
            }
        }
        __syncthreads();
        buf = (buf + 1) % STAGES;
    }

    // epilogue: add bias, store float2 pairs
    #pragma unroll
    for (int nt = 0; nt < 4; nt++) {
        int n = n0 + wid * 32 + nt * 8 + c * 2;
        float bx = b2[n], by = b2[n + 1];
        #pragma unroll
        for (int mt = 0; mt < 4; mt++) {
            int m = mt * 16 + r;
            float2 o0 = make_float2(acc[mt][nt][0] + bx, acc[mt][nt][1] + by);
            float2 o1 = make_float2(acc[mt][nt][2] + bx, acc[mt][nt][3] + by);
            *reinterpret_cast<float2*>(&g_v[m       * NOUT + n]) = o0;
            *reinterpret_cast<float2*>(&g_v[(m + 8) * NOUT + n]) = o1;
        }
    }
}

// ---------------------------------------------------------------------------
// Kernel 3: dense output writer. 4 (b,i)-rows per block for store MLP;
// float4 streaming stores. k[b,i,j] = 0.5*(v[b,i,j-lo_i] + v[b,j,i-lo_j])
// + (i==j) inside the band, else 0.
// ---------------------------------------------------------------------------
__global__ void __launch_bounds__(256) k3_scatter(float* __restrict__ out) {
    const int base = blockIdx.x * 4;
    const int t  = threadIdx.x;
    const int j0 = t * 4;

    #pragma unroll
    for (int rr = 0; rr < 4; rr++) {
        const int bi = base + rr;
        const int i  = bi & (DDIM - 1);
        const int b  = bi >> 10;
        const int lo = (i > 16) ? i - 16 : 0;
        const int hi = (i < DDIM - 17) ? i + 16 : DDIM - 1;

        float4 val = make_float4(0.f, 0.f, 0.f, 0.f);
        if (j0 + 3 >= lo && j0 <= hi) {
            const float* vb = g_v + b * NOUT;
            float v4[4];
            #pragma unroll
            for (int e = 0; e < 4; e++) {
                int j = j0 + e;
                float x = 0.f;
                if (j >= lo && j <= hi) {
                    float t1  = vb[i * MNZ + (j - lo)];
                    int   loj = (j > 16) ? j - 16 : 0;
                    float t2  = vb[j * MNZ + (i - loj)];
                    x = 0.5f * (t1 + t2);
                    if (j == i) x += 1.0f;
                }
                v4[e] = x;
            }
            val = make_float4(v4[0], v4[1], v4[2], v4[3]);
        }
        __stcs(reinterpret_cast<float4*>(out + (size_t)bi * DDIM) + t, val);
    }
}

// ---------------------------------------------------------------------------
extern "C" void kernel_launch(void* const* d_in, const int* in_sizes, int n_in,
                              void* d_out, int out_size) {
    const float* z  = (const float*)d_in[0];
    // d_in[1] = mask (unused: band structure is analytic)
    const float* W1 = (const float*)d_in[2];
    const float* b1 = (const float*)d_in[3];
    const float* W2 = (const float*)d_in[4];
    const float* b2 = (const float*)d_in[5];
    // d_in[6] = idx (unused: idx[i][m] == max(0,i-16)+m on the valid range)
    float* out = (float*)d_out;

    cudaFuncSetAttribute(k2_gemm,
                         cudaFuncAttributeMaxDynamicSharedMemorySize, K2_SMEM);
    k1_mlp_gelu<<<128, 256>>>(z, W1, b1);
    k2_gemm<<<NOUT / BN, 256, K2_SMEM>>>(W2, b2);
    k3_scatter<<<BATCH * DDIM / 4, 256>>>(out);
}

// round 5
// speedup vs baseline: 1.4658x; 1.1999x over previous
#include <cuda_runtime.h>
#include <cstdint>

#define BATCH 64
#define LDIM  256
#define HDIM  1024
#define DDIM  1024
#define MNZ   33
#define NOUT  (DDIM*MNZ)   // 33792

// scratch (device globals: no allocation allowed)
__device__ float g_h[BATCH*HDIM];   // 256 KB (stored pre-rounded to tf32)
__device__ float g_v[BATCH*NOUT];   // 8.6 MB

__device__ __forceinline__ uint32_t f2tf(float x) {
    uint32_t r; asm("cvt.rna.tf32.f32 %0, %1;\n" : "=r"(r) : "f"(x)); return r;
}

// ---------------------------------------------------------------------------
// Kernel 1: h = gelu(z @ W1 + b1), exact (erf) GELU.
// Warp-level K-split: block = 32 j x 8 batches, 8 warps; warp w owns
// k in [32w, 32w+32) -> 32 INDEPENDENT coalesced 128B W1 loads per lane
// (MLP ~32, no serial chain), z broadcast from smem, 8-way smem reduction.
// grid = (1024/32) x (64/8) = 256 CTAs. Output pre-rounded to tf32.
// ---------------------------------------------------------------------------
#define K1_JT 32
#define K1_BT 8

__global__ void __launch_bounds__(256) k1_mlp_gelu(
        const float* __restrict__ z,
        const float* __restrict__ W1,
        const float* __restrict__ b1) {
    __shared__ float sz[K1_BT * LDIM];          // 8 KB: z rows b0..b0+7
    __shared__ float red[8][K1_BT][K1_JT];      // 8 KB: per-warp partials
    const int t    = threadIdx.x;
    const int w    = t >> 5;
    const int lane = t & 31;
    const int j0   = blockIdx.x * K1_JT;
    const int b0   = blockIdx.y * K1_BT;
    const int j    = j0 + lane;

    #pragma unroll
    for (int i = t; i < K1_BT * LDIM; i += 256)
        sz[i] = z[(b0 + (i >> 8)) * LDIM + (i & (LDIM - 1))];
    __syncthreads();

    float acc[K1_BT];
    #pragma unroll
    for (int b = 0; b < K1_BT; b++) acc[b] = 0.f;

    const float* wp = W1 + j;
    #pragma unroll
    for (int kk = 0; kk < 32; kk++) {
        const int k = w * 32 + kk;
        const float wv = wp[k * HDIM];          // coalesced 128B per warp
        #pragma unroll
        for (int b = 0; b < K1_BT; b++)
            acc[b] += sz[b * LDIM + k] * wv;    // smem broadcast
    }
    #pragma unroll
    for (int b = 0; b < K1_BT; b++) red[w][b][lane] = acc[b];
    __syncthreads();

    {   // t -> (b = t>>5, lane): reduce 8 warps, bias, gelu, store
        const int b = t >> 5;
        float s = 0.f;
        #pragma unroll
        for (int w2 = 0; w2 < 8; w2++) s += red[w2][b][lane];
        s += b1[j];
        float g = 0.5f * s * (1.0f + erff(s * 0.70710678118654752f));
        g_h[(b0 + b) * HDIM + j] = __uint_as_float(f2tf(g));
    }
}

// ---------------------------------------------------------------------------
// Kernel 2: v = h @ W2 + b2  (64 x 33792, K=1024), tf32 mma.sync, fp32 accum.
// CTA tile 64x256, 256 threads (8 warps x 64x32), BK=16, 3-stage cp.async.
// grid = 132 CTAs = single wave. A fragments are pre-rounded tf32 bits
// (no cvt in inner loop); B converted with cvt.rna. BSTRIDE=264 (mod 32 = 8)
// -> conflict-free B fragment LDS.
// ---------------------------------------------------------------------------
#define BN 256
#define BK 16
#define STAGES 3
#define ASTRIDE 20            // 64 rows x (16+4)
#define BSTRIDE 264           // 256 + 8: banks (c*8+r) all distinct
#define A_ELEMS (64 * ASTRIDE)
#define B_ELEMS (BK * BSTRIDE)
#define NSTAGE (HDIM / BK)    // 64
#define K2_SMEM (STAGES * (A_ELEMS + B_ELEMS) * 4)   // 66048 B

__device__ __forceinline__ void cp16(float* s, const float* g) {
    uint32_t a = (uint32_t)__cvta_generic_to_shared(s);
    asm volatile("cp.async.cg.shared.global [%0], [%1], 16;\n" :: "r"(a), "l"(g));
}
__device__ __forceinline__ void mma8(float* d, const uint32_t* a, uint32_t b0, uint32_t b1) {
    asm volatile("mma.sync.aligned.m16n8k8.row.col.f32.tf32.tf32.f32 "
                 "{%0,%1,%2,%3}, {%4,%5,%6,%7}, {%8,%9}, {%0,%1,%2,%3};\n"
                 : "+f"(d[0]), "+f"(d[1]), "+f"(d[2]), "+f"(d[3])
                 : "r"(a[0]), "r"(a[1]), "r"(a[2]), "r"(a[3]), "r"(b0), "r"(b1));
}

__global__ void __launch_bounds__(256) k2_gemm(const float* __restrict__ W2,
                                               const float* __restrict__ b2) {
    extern __shared__ float sm2[];
    float* Asm = sm2;                          // [STAGES][A_ELEMS]
    float* Bsm = sm2 + STAGES * A_ELEMS;       // [STAGES][B_ELEMS]
    const int t    = threadIdx.x;
    const int wid  = t >> 5;
    const int lane = t & 31;
    const int n0   = blockIdx.x * BN;
    const int r = lane >> 2, c = lane & 3;

    float acc[4][4][4];
    #pragma unroll
    for (int i = 0; i < 4; i++)
        #pragma unroll
        for (int j = 0; j < 4; j++)
            #pragma unroll
            for (int e = 0; e < 4; e++) acc[i][j][e] = 0.f;

    auto load_stage = [&](int s, int buf) {
        const int k0 = s * BK;
        {   // A: 64x16 = 256 float4 -> 1 per thread
            int m = t >> 2, kk4 = (t & 3) * 4;
            cp16(&Asm[buf * A_ELEMS + m * ASTRIDE + kk4], g_h + m * HDIM + k0 + kk4);
        }
        #pragma unroll
        for (int i = 0; i < 4; i++) {           // B: 16x256 = 1024 float4
            int f = t + 256 * i;
            int kk = f >> 6, nn4 = (f & 63) * 4;
            cp16(&Bsm[buf * B_ELEMS + kk * BSTRIDE + nn4], W2 + (k0 + kk) * NOUT + n0 + nn4);
        }
        asm volatile("cp.async.commit_group;\n" ::: "memory");
    };

    load_stage(0, 0);
    load_stage(1, 1);
    int buf = 0;
    #pragma unroll 1
    for (int s = 0; s < NSTAGE; s++) {
        if (s + 2 < NSTAGE) {
            load_stage(s + 2, (buf + 2) % STAGES);
            asm volatile("cp.async.wait_group 2;\n" ::: "memory");
        } else if (s + 1 < NSTAGE) {
            asm volatile("cp.async.wait_group 1;\n" ::: "memory");
        } else {
            asm volatile("cp.async.wait_group 0;\n" ::: "memory");
        }
        __syncthreads();
        const uint32_t* A = reinterpret_cast<const uint32_t*>(Asm + buf * A_ELEMS);
        const float*    Bb = Bsm + buf * B_ELEMS;
        #pragma unroll
        for (int kk = 0; kk < BK; kk += 8) {
            uint32_t af[4][4];
            #pragma unroll
            for (int mt = 0; mt < 4; mt++) {
                int mr = mt * 16 + r;
                af[mt][0] = A[mr       * ASTRIDE + kk + c];
                af[mt][1] = A[(mr + 8) * ASTRIDE + kk + c];
                af[mt][2] = A[mr       * ASTRIDE + kk + c + 4];
                af[mt][3] = A[(mr + 8) * ASTRIDE + kk + c + 4];
            }
            #pragma unroll
            for (int nt = 0; nt < 4; nt++) {
                int nb = wid * 32 + nt * 8 + r;
                uint32_t b0 = f2tf(Bb[(kk + c)     * BSTRIDE + nb]);
                uint32_t b1 = f2tf(Bb[(kk + c + 4) * BSTRIDE + nb]);
                #pragma unroll
                for (int mt = 0; mt < 4; mt++)
                    mma8(acc[mt][nt], af[mt], b0, b1);
            }
        }
        __syncthreads();
        buf = (buf + 1) % STAGES;
    }

    // epilogue: add bias, store float2 pairs
    #pragma unroll
    for (int nt = 0; nt < 4; nt++) {
        int n = n0 + wid * 32 + nt * 8 + c * 2;
        float bx = b2[n], by = b2[n + 1];
        #pragma unroll
        for (int mt = 0; mt < 4; mt++) {
            int m = mt * 16 + r;
            float2 o0 = make_float2(acc[mt][nt][0] + bx, acc[mt][nt][1] + by);
            float2 o1 = make_float2(acc[mt][nt][2] + bx, acc[mt][nt][3] + by);
            *reinterpret_cast<float2*>(&g_v[m       * NOUT + n]) = o0;
            *reinterpret_cast<float2*>(&g_v[(m + 8) * NOUT + n]) = o1;
        }
    }
}

// ---------------------------------------------------------------------------
// Kernel 3: dense output writer. 4 (b,i)-rows per block for store MLP;
// float4 streaming stores. k[b,i,j] = 0.5*(v[b,i,j-lo_i] + v[b,j,i-lo_j])
// + (i==j) inside the band, else 0.
// ---------------------------------------------------------------------------
__global__ void __launch_bounds__(256) k3_scatter(float* __restrict__ out) {
    const int base = blockIdx.x * 4;
    const int t  = threadIdx.x;
    const int j0 = t * 4;

    #pragma unroll
    for (int rr = 0; rr < 4; rr++) {
        const int bi = base + rr;
        const int i  = bi & (DDIM - 1);
        const int b  = bi >> 10;
        const int lo = (i > 16) ? i - 16 : 0;
        const int hi = (i < DDIM - 17) ? i + 16 : DDIM - 1;

        float4 val = make_float4(0.f, 0.f, 0.f, 0.f);
        if (j0 + 3 >= lo && j0 <= hi) {
            const float* vb = g_v + b * NOUT;
            float v4[4];
            #pragma unroll
            for (int e = 0; e < 4; e++) {
                int j = j0 + e;
                float x = 0.f;
                if (j >= lo && j <= hi) {
                    float t1  = vb[i * MNZ + (j - lo)];
                    int   loj = (j > 16) ? j - 16 : 0;
                    float t2  = vb[j * MNZ + (i - loj)];
                    x = 0.5f * (t1 + t2);
                    if (j == i) x += 1.0f;
                }
                v4[e] = x;
            }
            val = make_float4(v4[0], v4[1], v4[2], v4[3]);
        }
        __stcs(reinterpret_cast<float4*>(out + (size_t)bi * DDIM) + t, val);
    }
}

// ---------------------------------------------------------------------------
extern "C" void kernel_launch(void* const* d_in, const int* in_sizes, int n_in,
                              void* d_out, int out_size) {
    const float* z  = (const float*)d_in[0];
    // d_in[1] = mask (unused: band structure is analytic)
    const float* W1 = (const float*)d_in[2];
    const float* b1 = (const float*)d_in[3];
    const float* W2 = (const float*)d_in[4];
    const float* b2 = (const float*)d_in[5];
    // d_in[6] = idx (unused: idx[i][m] == max(0,i-16)+m on the valid range)
    float* out = (float*)d_out;

    cudaFuncSetAttribute(k2_gemm,
                         cudaFuncAttributeMaxDynamicSharedMemorySize, K2_SMEM);
    dim3 g1(HDIM / K1_JT, BATCH / K1_BT);   // (32, 8)
    k1_mlp_gelu<<<g1, 256>>>(z, W1, b1);
    k2_gemm<<<NOUT / BN, 256, K2_SMEM>>>(W2, b2);
    k3_scatter<<<BATCH * DDIM / 4, 256>>>(out);
}

// round 6
// speedup vs baseline: 1.5104x; 1.0304x over previous
#include <cuda_runtime.h>
#include <cstdint>

#define BATCH 64
#define LDIM  256
#define HDIM  1024
#define DDIM  1024
#define MNZ   33
#define NOUT  (DDIM*MNZ)   // 33792

// scratch (device globals: no allocation allowed)
__device__ float g_h[BATCH*HDIM];   // 256 KB (stored pre-rounded to tf32)
__device__ float g_v[BATCH*NOUT];   // 8.6 MB

__device__ __forceinline__ uint32_t f2tf(float x) {
    uint32_t r; asm("cvt.rna.tf32.f32 %0, %1;\n" : "=r"(r) : "f"(x)); return r;
}

// ---------------------------------------------------------------------------
// Kernel 1: h = gelu(z @ W1 + b1), exact (erf) GELU.
// Warp-level K-split: block = 32 j x 4 batches, 8 warps; warp w owns
// k in [32w, 32w+32) -> 32 independent coalesced 128B W1 loads per lane,
// z broadcast from smem, 8-way smem reduction. grid = 32 x 16 = 512 CTAs.
// Output pre-rounded to tf32 so k2 skips A-side cvt.
// ---------------------------------------------------------------------------
#define K1_JT 32
#define K1_BT 4

__global__ void __launch_bounds__(256) k1_mlp_gelu(
        const float* __restrict__ z,
        const float* __restrict__ W1,
        const float* __restrict__ b1) {
    __shared__ float sz[K1_BT * LDIM];          // 4 KB
    __shared__ float red[8][K1_BT][K1_JT];      // 4 KB
    const int t    = threadIdx.x;
    const int w    = t >> 5;
    const int lane = t & 31;
    const int j0   = blockIdx.x * K1_JT;
    const int b0   = blockIdx.y * K1_BT;
    const int j    = j0 + lane;

    #pragma unroll
    for (int i = t; i < K1_BT * LDIM; i += 256)
        sz[i] = z[(b0 + (i >> 8)) * LDIM + (i & (LDIM - 1))];
    __syncthreads();

    float acc[K1_BT];
    #pragma unroll
    for (int b = 0; b < K1_BT; b++) acc[b] = 0.f;

    const float* wp = W1 + j;
    #pragma unroll
    for (int kk = 0; kk < 32; kk++) {
        const int k = w * 32 + kk;
        const float wv = wp[k * HDIM];          // coalesced 128B per warp
        #pragma unroll
        for (int b = 0; b < K1_BT; b++)
            acc[b] += sz[b * LDIM + k] * wv;    // smem broadcast
    }
    #pragma unroll
    for (int b = 0; b < K1_BT; b++) red[w][b][lane] = acc[b];
    __syncthreads();

    if (t < 32 * K1_BT) {                        // t -> (b = t>>5, lane)
        const int b = t >> 5;
        float s = 0.f;
        #pragma unroll
        for (int w2 = 0; w2 < 8; w2++) s += red[w2][b][lane];
        s += b1[j];
        float g = 0.5f * s * (1.0f + erff(s * 0.70710678118654752f));
        g_h[(b0 + b) * HDIM + j] = __uint_as_float(f2tf(g));
    }
}

// ---------------------------------------------------------------------------
// Kernel 2: v = h @ W2 + b2  (64 x 33792, K=1024), tf32 mma.sync, fp32 accum.
// CTA tile 64x256, 256 threads = 8 warps = (2 K-groups) x (4 N-quads).
// Each warp computes the full 64x64 tile of its N-quad over HALF the BK
// (K-split) -> fragment LDS 48KB -> 32KB per stage. 4-stage cp.async.
// grid = 132 CTAs = single wave. Epilogue: cross-K-group smem reduction,
// then bias + store. A frags pre-rounded tf32 bits (no cvt); B cvt.rna.
// ---------------------------------------------------------------------------
#define BN 256
#define BK 16
#define STAGES 4
#define ASTRIDE 20            // 64 rows x (16+4)
#define BSTRIDE 264           // 256 + 8: banks (8c + r) all distinct
#define A_ELEMS (64 * ASTRIDE)     // 1280
#define B_ELEMS (BK * BSTRIDE)     // 4224
#define NSTAGE (HDIM / BK)    // 64
#define K2_SMEM (STAGES * (A_ELEMS + B_ELEMS) * 4)   // 88064 B

__device__ __forceinline__ void cp16(float* s, const float* g) {
    uint32_t a = (uint32_t)__cvta_generic_to_shared(s);
    asm volatile("cp.async.cg.shared.global [%0], [%1], 16;\n" :: "r"(a), "l"(g));
}
__device__ __forceinline__ void mma8(float* d, const uint32_t* a, uint32_t b0, uint32_t b1) {
    asm volatile("mma.sync.aligned.m16n8k8.row.col.f32.tf32.tf32.f32 "
                 "{%0,%1,%2,%3}, {%4,%5,%6,%7}, {%8,%9}, {%0,%1,%2,%3};\n"
                 : "+f"(d[0]), "+f"(d[1]), "+f"(d[2]), "+f"(d[3])
                 : "r"(a[0]), "r"(a[1]), "r"(a[2]), "r"(a[3]), "r"(b0), "r"(b1));
}

__global__ void __launch_bounds__(256) k2_gemm(const float* __restrict__ W2,
                                               const float* __restrict__ b2) {
    extern __shared__ float sm2[];
    float* Asm = sm2;                          // [STAGES][A_ELEMS]
    float* Bsm = sm2 + STAGES * A_ELEMS;       // [STAGES][B_ELEMS]
    const int t    = threadIdx.x;
    const int wid  = t >> 5;
    const int lane = t & 31;
    const int grp  = wid >> 2;     // K-group: 0 -> kk 0..7, 1 -> kk 8..15
    const int q    = wid & 3;      // N-quad (64 cols each)
    const int kb   = grp * 8;
    const int n0   = blockIdx.x * BN;
    const int r = lane >> 2, c = lane & 3;

    float acc[4][8][4];
    #pragma unroll
    for (int i = 0; i < 4; i++)
        #pragma unroll
        for (int j = 0; j < 8; j++)
            #pragma unroll
            for (int e = 0; e < 4; e++) acc[i][j][e] = 0.f;

    auto load_stage = [&](int s, int buf) {
        const int k0 = s * BK;
        {   // A: 64x16 = 256 float4 -> 1 per thread
            int m = t >> 2, kk4 = (t & 3) * 4;
            cp16(&Asm[buf * A_ELEMS + m * ASTRIDE + kk4], g_h + m * HDIM + k0 + kk4);
        }
        #pragma unroll
        for (int i = 0; i < 4; i++) {           // B: 16x256 = 1024 float4
            int f = t + 256 * i;
            int kk = f >> 6, nn4 = (f & 63) * 4;
            cp16(&Bsm[buf * B_ELEMS + kk * BSTRIDE + nn4], W2 + (k0 + kk) * NOUT + n0 + nn4);
        }
        asm volatile("cp.async.commit_group;\n" ::: "memory");
    };

    load_stage(0, 0);
    load_stage(1, 1);
    load_stage(2, 2);
    int buf = 0;
    #pragma unroll 1
    for (int s = 0; s < NSTAGE; s++) {
        if (s + 3 < NSTAGE) {
            load_stage(s + 3, (buf + 3) & 3);
            asm volatile("cp.async.wait_group 3;\n" ::: "memory");
        } else if (s + 2 < NSTAGE) {
            asm volatile("cp.async.wait_group 2;\n" ::: "memory");
        } else if (s + 1 < NSTAGE) {
            asm volatile("cp.async.wait_group 1;\n" ::: "memory");
        } else {
            asm volatile("cp.async.wait_group 0;\n" ::: "memory");
        }
        __syncthreads();
        const uint32_t* A = reinterpret_cast<const uint32_t*>(Asm + buf * A_ELEMS);
        const float*    Bb = Bsm + buf * B_ELEMS;

        uint32_t af[4][4];
        #pragma unroll
        for (int mt = 0; mt < 4; mt++) {
            int mr = mt * 16 + r;
            af[mt][0] = A[mr       * ASTRIDE + kb + c];
            af[mt][1] = A[(mr + 8) * ASTRIDE + kb + c];
            af[mt][2] = A[mr       * ASTRIDE + kb + c + 4];
            af[mt][3] = A[(mr + 8) * ASTRIDE + kb + c + 4];
        }
        #pragma unroll
        for (int nt = 0; nt < 8; nt++) {
            int nb = q * 64 + nt * 8 + r;
            uint32_t b0 = f2tf(Bb[(kb + c)     * BSTRIDE + nb]);
            uint32_t b1 = f2tf(Bb[(kb + c + 4) * BSTRIDE + nb]);
            #pragma unroll
            for (int mt = 0; mt < 4; mt++)
                mma8(acc[mt][nt], af[mt], b0, b1);
        }
        __syncthreads();
        buf = (buf + 1) & 3;
    }

    // epilogue: reduce the two K-groups through smem, then bias + store.
    __syncthreads();
    float* rbuf = sm2;                     // reuse pipeline smem (64 KB used)
    const int u = q * 32 + lane;           // matching lane pair across groups
    if (grp == 1) {
        #pragma unroll
        for (int mt = 0; mt < 4; mt++)
            #pragma unroll
            for (int nt = 0; nt < 8; nt++)
                #pragma unroll
                for (int e = 0; e < 4; e++)
                    rbuf[(mt * 32 + nt * 4 + e) * 128 + u] = acc[mt][nt][e];
    }
    __syncthreads();
    if (grp == 0) {
        #pragma unroll
        for (int mt = 0; mt < 4; mt++)
            #pragma unroll
            for (int nt = 0; nt < 8; nt++)
                #pragma unroll
                for (int e = 0; e < 4; e++)
                    acc[mt][nt][e] += rbuf[(mt * 32 + nt * 4 + e) * 128 + u];

        #pragma unroll
        for (int nt = 0; nt < 8; nt++) {
            int n = n0 + q * 64 + nt * 8 + c * 2;
            float bx = b2[n], by = b2[n + 1];
            #pragma unroll
            for (int mt = 0; mt < 4; mt++) {
                int m = mt * 16 + r;
                float2 o0 = make_float2(acc[mt][nt][0] + bx, acc[mt][nt][1] + by);
                float2 o1 = make_float2(acc[mt][nt][2] + bx, acc[mt][nt][3] + by);
                *reinterpret_cast<float2*>(&g_v[m       * NOUT + n]) = o0;
                *reinterpret_cast<float2*>(&g_v[(m + 8) * NOUT + n]) = o1;
            }
        }
    }
}

// ---------------------------------------------------------------------------
// Kernel 3: dense output writer. 4 (b,i)-rows per block for store MLP;
// float4 streaming stores. k[b,i,j] = 0.5*(v[b,i,j-lo_i] + v[b,j,i-lo_j])
// + (i==j) inside the band, else 0.
// ---------------------------------------------------------------------------
__global__ void __launch_bounds__(256) k3_scatter(float* __restrict__ out) {
    const int base = blockIdx.x * 4;
    const int t  = threadIdx.x;
    const int j0 = t * 4;

    #pragma unroll
    for (int rr = 0; rr < 4; rr++) {
        const int bi = base + rr;
        const int i  = bi & (DDIM - 1);
        const int b  = bi >> 10;
        const int lo = (i > 16) ? i - 16 : 0;
        const int hi = (i < DDIM - 17) ? i + 16 : DDIM - 1;

        float4 val = make_float4(0.f, 0.f, 0.f, 0.f);
        if (j0 + 3 >= lo && j0 <= hi) {
            const float* vb = g_v + b * NOUT;
            float v4[4];
            #pragma unroll
            for (int e = 0; e < 4; e++) {
                int j = j0 + e;
                float x = 0.f;
                if (j >= lo && j <= hi) {
                    float t1  = vb[i * MNZ + (j - lo)];
                    int   loj = (j > 16) ? j - 16 : 0;
                    float t2  = vb[j * MNZ + (i - loj)];
                    x = 0.5f * (t1 + t2);
                    if (j == i) x += 1.0f;
                }
                v4[e] = x;
            }
            val = make_float4(v4[0], v4[1], v4[2], v4[3]);
        }
        __stcs(reinterpret_cast<float4*>(out + (size_t)bi * DDIM) + t, val);
    }
}

// ---------------------------------------------------------------------------
extern "C" void kernel_launch(void* const* d_in, const int* in_sizes, int n_in,
                              void* d_out, int out_size) {
    const float* z  = (const float*)d_in[0];
    // d_in[1] = mask (unused: band structure is analytic)
    const float* W1 = (const float*)d_in[2];
    const float* b1 = (const float*)d_in[3];
    const float* W2 = (const float*)d_in[4];
    const float* b2 = (const float*)d_in[5];
    // d_in[6] = idx (unused: idx[i][m] == max(0,i-16)+m on the valid range)
    float* out = (float*)d_out;

    cudaFuncSetAttribute(k2_gemm,
                         cudaFuncAttributeMaxDynamicSharedMemorySize, K2_SMEM);
    dim3 g1(HDIM / K1_JT, BATCH / K1_BT);   // (32, 16)
    k1_mlp_gelu<<<g1, 256>>>(z, W1, b1);
    k2_gemm<<<NOUT / BN, 256, K2_SMEM>>>(W2, b2);
    k3_scatter<<<BATCH * DDIM / 4, 256>>>(out);
}